// round 4
// baseline (speedup 1.0000x reference)
#include <cuda_runtime.h>
#include <cuda_bf16.h>

typedef unsigned int u32;

#define TPB 384
#define NW  12   // warps per CTA

// SMEM: B-frag bank 64KB | consts 2KB | per-thread stash (h1,hd1) 96KB
#define CONST_OFF 65536
#define STASH_OFF (65536 + 2048)
#define SMEM_BYTES (STASH_OFF + TPB * 64 * 4)   // 165888

__device__ __forceinline__ float ftanh(float x) {
    float e; asm("ex2.approx.f32 %0, %1;" : "=f"(e) : "f"(x * 2.8853900817779268f));
    float r; asm("rcp.approx.f32 %0, %1;" : "=f"(r) : "f"(e + 1.0f));
    return fmaf(-2.0f, r, 1.0f);
}

// split (a,b) -> packed bf16x2 hi + residual lo
__device__ __forceinline__ void split2(float a, float b, u32 &hi, u32 &lo) {
    __nv_bfloat162 h2 = __floats2bfloat162_rn(a, b);
    hi = *reinterpret_cast<u32*>(&h2);
    float ar = __bfloat162float(__low2bfloat16(h2));
    float br = __bfloat162float(__high2bfloat16(h2));
    __nv_bfloat162 l2 = __floats2bfloat162_rn(a - ar, b - br);
    lo = *reinterpret_cast<u32*>(&l2);
}

__device__ __forceinline__ void mma16816(float* d, const u32* a, u32 b0, u32 b1) {
    asm volatile(
        "mma.sync.aligned.m16n8k16.row.col.f32.bf16.bf16.f32 "
        "{%0,%1,%2,%3},{%4,%5,%6,%7},{%8,%9},{%0,%1,%2,%3};"
        : "+f"(d[0]), "+f"(d[1]), "+f"(d[2]), "+f"(d[3])
        : "r"(a[0]), "r"(a[1]), "r"(a[2]), "r"(a[3]), "r"(b0), "r"(b1));
}

// one pass: acc[8][4] = Fhi/Flo [16,64] x B_stage [64,64], 3-term bf16 split
#define RUN_PASS(S, ACC, FH, FL) do {                                         \
    _Pragma("unroll")                                                         \
    for (int nt = 0; nt < 8; nt++)                                            \
        { _Pragma("unroll") for (int j = 0; j < 4; j++) (ACC)[nt][j] = 0.f; } \
    _Pragma("unroll")                                                         \
    for (int kt = 0; kt < 4; kt++) {                                          \
        _Pragma("unroll")                                                     \
        for (int nt = 0; nt < 8; nt++) {                                      \
            uint4 bf = bfr[(((S) * 4 + kt) * 8 + nt) * 32 + lane];            \
            mma16816((ACC)[nt], (FH)[kt], bf.x, bf.y);                        \
            mma16816((ACC)[nt], (FH)[kt], bf.z, bf.w);                        \
            mma16816((ACC)[nt], (FL)[kt], bf.x, bf.y);                        \
        }                                                                     \
    }                                                                         \
} while (0)

// D (m16n8) ntiles (2kt,2kt+1) == A (m16k16) ktile kt, reg-for-reg.
#define PACK_SET(ACC, FH, FL) do {                                            \
    _Pragma("unroll")                                                         \
    for (int kt = 0; kt < 4; kt++) {                                          \
        split2((ACC)[2*kt][0],   (ACC)[2*kt][1],   (FH)[kt][0], (FL)[kt][0]); \
        split2((ACC)[2*kt][2],   (ACC)[2*kt][3],   (FH)[kt][1], (FL)[kt][1]); \
        split2((ACC)[2*kt+1][0], (ACC)[2*kt+1][1], (FH)[kt][2], (FL)[kt][2]); \
        split2((ACC)[2*kt+1][2], (ACC)[2*kt+1][3], (FH)[kt][3], (FL)[kt][3]); \
    }                                                                         \
} while (0)

__global__ void __launch_bounds__(TPB, 1)
lnn_mma(const float2* __restrict__ X,
        const float* __restrict__ W0, const float* __restrict__ b0,
        const float* __restrict__ W1, const float* __restrict__ b1,
        const float* __restrict__ W2, const float* __restrict__ b2,
        const float* __restrict__ W3,
        float2* __restrict__ out, int B, int nchunks)
{
    extern __shared__ __align__(16) char sm[];
    uint4* bfr = (uint4*)sm;
    float* cs = (float*)(sm + CONST_OFF);
    float* w00f = cs;       float* w01f = cs + 64;
    float* b0f  = cs + 128; float* b1f  = cs + 192;
    float* b2f  = cs + 256; float* w3f  = cs + 320;
    float* stash = (float*)(sm + STASH_OFF);

    const int t = threadIdx.x;
    if (t < 64) {
        w00f[t] = W0[t];     w01f[t] = W0[64 + t];
        b0f[t]  = b0[t];     b1f[t]  = b1[t];
        b2f[t]  = b2[t];     w3f[t]  = W3[t];
    }
    // pre-pack weight B-fragments (hi/lo bf16):
    // s0: W1 (F1), s1: W2 (F2), s2: W2^T (B1), s3: W1^T (B0)
    for (int i = t; i < 4096; i += TPB) {
        int ln = i & 31, nt = (i >> 5) & 7, kt = (i >> 8) & 3, s = i >> 10;
        int k0 = kt * 16 + (ln & 3) * 2;
        int n  = nt * 8 + (ln >> 2);
        float v0, v1, v2, v3;
        if (s == 0) {
            v0 = W1[k0*64+n]; v1 = W1[(k0+1)*64+n];
            v2 = W1[(k0+8)*64+n]; v3 = W1[(k0+9)*64+n];
        } else if (s == 1) {
            v0 = W2[k0*64+n]; v1 = W2[(k0+1)*64+n];
            v2 = W2[(k0+8)*64+n]; v3 = W2[(k0+9)*64+n];
        } else if (s == 2) {
            v0 = W2[n*64+k0]; v1 = W2[n*64+k0+1];
            v2 = W2[n*64+k0+8]; v3 = W2[n*64+k0+9];
        } else {
            v0 = W1[n*64+k0]; v1 = W1[n*64+k0+1];
            v2 = W1[n*64+k0+8]; v3 = W1[n*64+k0+9];
        }
        u32 h0, l0, h1, l1;
        split2(v0, v1, h0, l0);
        split2(v2, v3, h1, l1);
        bfr[i] = make_uint4(h0, h1, l0, l1);
    }
    __syncthreads();

    const int lane = t & 31, warp = t >> 5;
    const int qr = lane >> 2;
    const int qc = (lane & 3) * 2;
    // lane-interleaved stash: [warp][idx 0..63][lane]
    float* st = stash + warp * (64 * 32) + lane;

    for (int chunk = blockIdx.x * NW + warp; chunk < nchunks;
         chunk += gridDim.x * NW) {
        const int r0 = chunk * 16 + qr, r1 = r0 + 8;
        float2 x0 = (r0 < B) ? X[r0] : make_float2(0.f, 0.f);
        float2 x1 = (r1 < B) ? X[r1] : make_float2(0.f, 0.f);
        const float q0 = x0.x, v0 = x0.y, q1 = x1.x, v1 = x1.y;

        u32 Ah[4][4], Al[4][4], Th[4][4], Tl[4][4];

        // ===== F0: h0 / hd0 A-fragments =====
#pragma unroll
        for (int kt = 0; kt < 4; kt++) {
#pragma unroll
            for (int hh = 0; hh < 2; hh++) {
                int k = kt * 16 + hh * 8 + qc;
                float wa = w00f[k], wb = w00f[k+1];
                float wc = w01f[k], wd = w01f[k+1];
                float ba = b0f[k],  bb = b0f[k+1];
                float z00 = fmaf(q0, wa, fmaf(v0, wc, ba));
                float z01 = fmaf(q0, wb, fmaf(v0, wd, bb));
                float z10 = fmaf(q1, wa, fmaf(v1, wc, ba));
                float z11 = fmaf(q1, wb, fmaf(v1, wd, bb));
                float h00 = ftanh(z00), h01 = ftanh(z01);
                float h10 = ftanh(z10), h11 = ftanh(z11);
                float d00 = fmaf(-h00, h00, 1.f) * wc;
                float d01 = fmaf(-h01, h01, 1.f) * wd;
                float d10 = fmaf(-h10, h10, 1.f) * wc;
                float d11 = fmaf(-h11, h11, 1.f) * wd;
                split2(h00, h01, Ah[kt][hh*2],   Al[kt][hh*2]);
                split2(h10, h11, Ah[kt][hh*2+1], Al[kt][hh*2+1]);
                split2(d00, d01, Th[kt][hh*2],   Tl[kt][hh*2]);
                split2(d10, d11, Th[kt][hh*2+1], Tl[kt][hh*2+1]);
            }
        }

        float zacc[8][4], dacc[8][4], u[8][4];

        // ===== F1 value: z1 -> h1 (stash) -> A' =====
        RUN_PASS(0, zacc, Ah, Al);
#pragma unroll
        for (int nt = 0; nt < 8; nt++)
#pragma unroll
            for (int j = 0; j < 4; j++) {
                int col = nt * 8 + qc + (j & 1);
                float h = ftanh(zacc[nt][j] + b1f[col]);
                st[(nt * 4 + j) * 32] = h;
                u[nt][j] = fmaf(-h, h, 1.f);
                zacc[nt][j] = h;
            }
        PACK_SET(zacc, Ah, Al);
        // ===== F1 tangent: zd1 -> hd1 (stash) -> T' =====
        RUN_PASS(0, dacc, Th, Tl);
#pragma unroll
        for (int nt = 0; nt < 8; nt++)
#pragma unroll
            for (int j = 0; j < 4; j++) {
                float hd = u[nt][j] * dacc[nt][j];
                st[(32 + nt * 4 + j) * 32] = hd;
                dacc[nt][j] = hd;
            }
        PACK_SET(dacc, Th, Tl);

        // ===== F2 value: z2 -> d2 -> A'; keep s=-2*w3*h2*u2 =====
        RUN_PASS(1, zacc, Ah, Al);
#pragma unroll
        for (int nt = 0; nt < 8; nt++)
#pragma unroll
            for (int j = 0; j < 4; j++) {
                int col = nt * 8 + qc + (j & 1);
                float h = ftanh(zacc[nt][j] + b2f[col]);
                float uu = fmaf(-h, h, 1.f);
                float w3v = w3f[col];
                zacc[nt][j] = w3v * uu;                 // d2
                u[nt][j] = -2.f * w3v * h * uu;         // s: dd2 = s * zd2
            }
        PACK_SET(zacc, Ah, Al);
        // ===== F2 tangent: dd2 = s * zd2 -> T' =====
        RUN_PASS(1, dacc, Th, Tl);
#pragma unroll
        for (int nt = 0; nt < 8; nt++)
#pragma unroll
            for (int j = 0; j < 4; j++)
                dacc[nt][j] = u[nt][j] * dacc[nt][j];
        PACK_SET(dacc, Th, Tl);

        // ===== B1 value: g1 -> d1 = g1*u1 -> A'; keep c=-2*g1*h1*hd1 =====
        RUN_PASS(2, zacc, Ah, Al);
#pragma unroll
        for (int nt = 0; nt < 8; nt++)
#pragma unroll
            for (int j = 0; j < 4; j++) {
                float g  = zacc[nt][j];
                float h  = st[(nt * 4 + j) * 32];
                float hd = st[(32 + nt * 4 + j) * 32];
                float uu = fmaf(-h, h, 1.f);
                zacc[nt][j] = g * uu;                    // d1
                u[nt][j] = -2.f * g * h * hd;            // c
            }
        PACK_SET(zacc, Ah, Al);
        // ===== B1 tangent: dd1 = gd1*u1 + c -> T' =====
        RUN_PASS(2, dacc, Th, Tl);
#pragma unroll
        for (int nt = 0; nt < 8; nt++)
#pragma unroll
            for (int j = 0; j < 4; j++) {
                float h = st[(nt * 4 + j) * 32];
                float uu = fmaf(-h, h, 1.f);
                dacc[nt][j] = fmaf(dacc[nt][j], uu, u[nt][j]);
            }
        PACK_SET(dacc, Th, Tl);

        // ===== B0 value: g0 -> p0; keep u0 and c0 =====
        float p00 = 0.f, p01 = 0.f, p02 = 0.f;
        float p10 = 0.f, p11 = 0.f, p12 = 0.f;
        RUN_PASS(3, zacc, Ah, Al);
#pragma unroll
        for (int nt = 0; nt < 8; nt++)
#pragma unroll
            for (int j = 0; j < 4; j++) {
                int k = nt * 8 + qc + (j & 1);
                int rh = j >> 1;
                float q = rh ? q1 : q0, v = rh ? v1 : v0;
                float wa = w00f[k], wc = w01f[k];
                float z0 = fmaf(q, wa, fmaf(v, wc, b0f[k]));
                float h = ftanh(z0);
                float uu = fmaf(-h, h, 1.f);
                float hd = uu * wc;
                float g = zacc[nt][j];
                float d0 = g * uu;
                if (rh) p10 = fmaf(d0, wa, p10);
                else    p00 = fmaf(d0, wa, p00);
                u[nt][j] = uu;
                zacc[nt][j] = -2.f * g * h * hd;         // c0
            }
        // ===== B0 tangent: dd0 = gd0*u0 + c0 -> p1, p2 =====
        RUN_PASS(3, dacc, Th, Tl);
#pragma unroll
        for (int nt = 0; nt < 8; nt++)
#pragma unroll
            for (int j = 0; j < 4; j++) {
                int k = nt * 8 + qc + (j & 1);
                float wa = w00f[k], wc = w01f[k];
                float dd0 = fmaf(dacc[nt][j], u[nt][j], zacc[nt][j]);
                if (j >> 1) {
                    p11 = fmaf(dd0, wa, p11);
                    p12 = fmaf(dd0, wc, p12);
                } else {
                    p01 = fmaf(dd0, wa, p01);
                    p02 = fmaf(dd0, wc, p02);
                }
            }
        // reduce across the 4 lanes of each quad (disjoint k's)
#pragma unroll
        for (int m = 1; m <= 2; m <<= 1) {
            p00 += __shfl_xor_sync(0xFFFFFFFFu, p00, m);
            p01 += __shfl_xor_sync(0xFFFFFFFFu, p01, m);
            p02 += __shfl_xor_sync(0xFFFFFFFFu, p02, m);
            p10 += __shfl_xor_sync(0xFFFFFFFFu, p10, m);
            p11 += __shfl_xor_sync(0xFFFFFFFFu, p11, m);
            p12 += __shfl_xor_sync(0xFFFFFFFFu, p12, m);
        }
        if ((lane & 3) == 0) {
            if (r0 < B) {
                float a = (p00 - p01 * v0) / (p02 + 0.1f);
                out[r0] = make_float2(v0, a);
            }
            if (r1 < B) {
                float a = (p10 - p11 * v1) / (p12 + 0.1f);
                out[r1] = make_float2(v1, a);
            }
        }
    }
}

extern "C" void kernel_launch(void* const* d_in, const int* in_sizes, int n_in,
                              void* d_out, int out_size) {
    const float* x  = (const float*)d_in[1];
    const float* W0 = (const float*)d_in[2];
    const float* b0 = (const float*)d_in[3];
    const float* W1 = (const float*)d_in[4];
    const float* b1 = (const float*)d_in[5];
    const float* W2 = (const float*)d_in[6];
    const float* b2 = (const float*)d_in[7];
    const float* W3 = (const float*)d_in[8];

    const int B = in_sizes[1] / 2;
    const int nchunks = (B + 15) / 16;

    int dev = 0, sms = 148;
    cudaGetDevice(&dev);
    cudaDeviceGetAttribute(&sms, cudaDevAttrMultiProcessorCount, dev);
    int grid = (nchunks + NW - 1) / NW;
    if (grid > sms) grid = sms;

    cudaFuncSetAttribute(lnn_mma, cudaFuncAttributeMaxDynamicSharedMemorySize,
                         SMEM_BYTES);
    lnn_mma<<<grid, TPB, SMEM_BYTES>>>((const float2*)x, W0, b0, W1, b1,
                                       W2, b2, W3, (float2*)d_out, B, nchunks);
}